// round 13
// baseline (speedup 1.0000x reference)
#include <cuda_runtime.h>
#include <cuda_fp16.h>
#include <math.h>
#include <stdint.h>

// ---------------------------------------------------------------------------
// TransformerBlock: B=8, N=1024, EMBED=768, HEADS=12, HEAD_DIM=64, HIDDEN=3072
// GEMMs: mma.sync.m16n8k16 fp16 + ldmatrix, 4 warps x (64x64), BK=64,
// 2-stage double buffer. Flash: full fp16, P kept in registers (C-frag of
// QK^T == A-frag of P@V), 3 CTAs/SM.
// ---------------------------------------------------------------------------

#define B_      8
#define N_      1024
#define EMBED_  768
#define HEADS_  12
#define HD_     64
#define HIDDEN_ 3072
#define TOKENS_ (B_ * N_)          // 8192
#define QKVW_   (3 * EMBED_)       // 2304

// ---- scratch (static device globals: allocation-free) ----
__device__ __half g_h16  [TOKENS_ * EMBED_];
__device__ __half g_qkv16[TOKENS_ * QKVW_];
__device__ __half g_ctx16[TOKENS_ * EMBED_];
__device__ float  g_x1   [TOKENS_ * EMBED_];
__device__ __half g_h216 [TOKENS_ * EMBED_];
__device__ __half g_ffn16[TOKENS_ * HIDDEN_];
// fp16 weights
__device__ __half g_wq16 [QKVW_  * EMBED_];
__device__ __half g_wp16 [EMBED_ * EMBED_];
__device__ __half g_w116 [HIDDEN_ * EMBED_];
__device__ __half g_w216 [EMBED_ * HIDDEN_];

// ---------------------------------------------------------------------------
// helpers
// ---------------------------------------------------------------------------
__device__ __forceinline__ uint32_t smem_u32(const void* p) {
    uint32_t a;
    asm("{ .reg .u64 t; cvta.to.shared.u64 t, %1; cvt.u32.u64 %0, t; }"
        : "=r"(a) : "l"(p));
    return a;
}
#define CP_ASYNC16(dst, src) \
    asm volatile("cp.async.cg.shared.global [%0], [%1], 16;" \
                 :: "r"(dst), "l"(src) : "memory")
#define CP_COMMIT()  asm volatile("cp.async.commit_group;" ::: "memory")
#define CP_WAIT0()   asm volatile("cp.async.wait_group 0;" ::: "memory")
#define CP_WAIT1()   asm volatile("cp.async.wait_group 1;" ::: "memory")

#define LDSM_X4(r0, r1, r2, r3, addr) \
    asm volatile("ldmatrix.sync.aligned.m8n8.x4.shared.b16 {%0,%1,%2,%3}, [%4];" \
                 : "=r"(r0), "=r"(r1), "=r"(r2), "=r"(r3) : "r"(addr))
#define LDSM_X4T(r0, r1, r2, r3, addr) \
    asm volatile("ldmatrix.sync.aligned.m8n8.x4.trans.shared.b16 {%0,%1,%2,%3}, [%4];" \
                 : "=r"(r0), "=r"(r1), "=r"(r2), "=r"(r3) : "r"(addr))

__device__ __forceinline__ void mma_f16(float* d, const uint32_t* a,
                                        const uint32_t* b) {
    asm volatile(
        "mma.sync.aligned.m16n8k16.row.col.f32.f16.f16.f32 "
        "{%0,%1,%2,%3}, {%4,%5,%6,%7}, {%8,%9}, {%0,%1,%2,%3};"
        : "+f"(d[0]), "+f"(d[1]), "+f"(d[2]), "+f"(d[3])
        : "r"(a[0]), "r"(a[1]), "r"(a[2]), "r"(a[3]), "r"(b[0]), "r"(b[1]));
}

// ---------------------------------------------------------------------------
// merged fp32 -> fp16 weight convert (all 4 weights, one launch)
// ---------------------------------------------------------------------------
#define NW1 (QKVW_  * EMBED_  / 4)
#define NW2 (EMBED_ * EMBED_  / 4)
#define NW3 (HIDDEN_ * EMBED_ / 4)
#define NW4 (EMBED_ * HIDDEN_ / 4)
#define NWTOT (NW1 + NW2 + NW3 + NW4)

__global__ __launch_bounds__(256) void f2h_all_kernel(
    const float* __restrict__ w1, const float* __restrict__ w2,
    const float* __restrict__ w3, const float* __restrict__ w4,
    __half* __restrict__ o1, __half* __restrict__ o2,
    __half* __restrict__ o3, __half* __restrict__ o4)
{
    int i = blockIdx.x * blockDim.x + threadIdx.x;
    if (i >= NWTOT) return;
    const float* src; __half* dst; int j = i;
    if (j < NW1)                { src = w1; dst = o1; }
    else if ((j -= NW1) < NW2)  { src = w2; dst = o2; }
    else if ((j -= NW2) < NW3)  { src = w3; dst = o3; }
    else                        { j -= NW3; src = w4; dst = o4; }
    float4 v = ((const float4*)src)[j];
    __half2 h0 = __floats2half2_rn(v.x, v.y);
    __half2 h1 = __floats2half2_rn(v.z, v.w);
    uint2 o;
    o.x = *(uint32_t*)&h0;
    o.y = *(uint32_t*)&h1;
    ((uint2*)dst)[j] = o;
}

// ---------------------------------------------------------------------------
// fp16 mma GEMM with ldmatrix: C = A @ W^T + bias (+res / +gelu)
// EPI: 0 = bias (fp16 out), 1 = bias + residual (fp32 out),
//      2 = bias + exact GELU (fp16 out)
// CTA 128x128, BK=64 halves, 128 thr / 4 warps (64x64/warp), 2 stages.
// Row stride 72 halves (144 B): ldmatrix rows land on 8 distinct 16B banks.
// ---------------------------------------------------------------------------
#define BK          64
#define RSH         72                          // row stride in halves
#define MAT_HALVES  (128 * RSH)                 // 9216
#define STAGE_HALVES (2 * MAT_HALVES)           // 18432
#define GEMM_DSMEM  (2 * STAGE_HALVES * 2)      // 73728 B

template <int EPI>
__global__ __launch_bounds__(128, 2) void mma_gemm(
    const __half* __restrict__ A, const __half* __restrict__ W,
    const float* __restrict__ bias, const float* __restrict__ res,
    void* __restrict__ Cv, int M, int Nn, int K)
{
    extern __shared__ __half smh[];

    const int tid  = threadIdx.x;
    const int wid  = tid >> 5, lane = tid & 31;
    const int mBase = blockIdx.y * 128;
    const int nBase = blockIdx.x * 128;
    const int warp_m = wid & 1;
    const int warp_n = wid >> 1;
    const int g = lane >> 2;
    const int q = lane & 3;
    const int m3 = lane >> 3, r8 = lane & 7;

    const uint32_t sm_base = smem_u32(smh);

    // cp.async: per matrix per ktile 128 rows x 8 chunks (16B) = 1024 chunks;
    // 8 chunks/thread. flat = tid + it*128: r = flat>>3, c8 = (flat&7)*8 halves.
    int rL[8], cL[8];
    #pragma unroll
    for (int it = 0; it < 8; it++) {
        int flat = tid + it * 128;
        rL[it] = flat >> 3;
        cL[it] = (flat & 7) << 3;
    }
    const __half* Arow = A + (size_t)mBase * K;
    const __half* Wrow = W + (size_t)nBase * K;

    const int nK = K / BK;

    // ldmatrix byte offsets (within a stage's A / W matrix)
    uint32_t aoff[4], boff[4];
    #pragma unroll
    for (int i = 0; i < 4; i++)
        aoff[i] = (uint32_t)(((warp_m * 64 + i * 16 + (m3 & 1) * 8 + r8) * RSH
                              + (m3 >> 1) * 8) * 2);
    #pragma unroll
    for (int p = 0; p < 4; p++)
        boff[p] = (uint32_t)(((warp_n * 64 + (2 * p + (m3 >> 1)) * 8 + r8) * RSH
                              + (m3 & 1) * 8) * 2);

    float acc[4][8][4];
    #pragma unroll
    for (int i = 0; i < 4; i++)
        #pragma unroll
        for (int j = 0; j < 8; j++)
            #pragma unroll
            for (int r = 0; r < 4; r++) acc[i][j][r] = 0.f;

    // ---- prologue: stage 0 ----
    #pragma unroll
    for (int it = 0; it < 8; it++) {
        uint32_t doff = (uint32_t)(rL[it] * RSH + cL[it]) * 2u;
        CP_ASYNC16(sm_base + doff,                   Arow + (size_t)rL[it] * K + cL[it]);
        CP_ASYNC16(sm_base + MAT_HALVES * 2u + doff, Wrow + (size_t)rL[it] * K + cL[it]);
    }
    CP_COMMIT();

    // ---- mainloop: 2-stage double buffer ----
    #pragma unroll 1
    for (int kt = 0; kt < nK; kt++) {
        CP_WAIT0();
        __syncthreads();   // stage kt ready; all warps done with slot (kt+1)&1

        int ft = kt + 1;
        if (ft < nK) {
            uint32_t sb = sm_base + (uint32_t)((ft & 1) * STAGE_HALVES) * 2u;
            int k0 = ft * BK;
            #pragma unroll
            for (int it = 0; it < 8; it++) {
                uint32_t doff = (uint32_t)(rL[it] * RSH + cL[it]) * 2u;
                CP_ASYNC16(sb + doff,                   Arow + (size_t)rL[it] * K + k0 + cL[it]);
                CP_ASYNC16(sb + MAT_HALVES * 2u + doff, Wrow + (size_t)rL[it] * K + k0 + cL[it]);
            }
        }
        CP_COMMIT();

        uint32_t sA = sm_base + (uint32_t)((kt & 1) * STAGE_HALVES) * 2u;
        uint32_t sW = sA + MAT_HALVES * 2u;

        #pragma unroll
        for (int ks = 0; ks < 4; ks++) {
            uint32_t ko = (uint32_t)(ks * 32);   // 16 halves per kstep
            uint32_t a[4][4], b[8][2];
            #pragma unroll
            for (int i = 0; i < 4; i++)
                LDSM_X4(a[i][0], a[i][1], a[i][2], a[i][3], sA + aoff[i] + ko);
            #pragma unroll
            for (int p = 0; p < 4; p++)
                LDSM_X4(b[2*p][0], b[2*p][1], b[2*p+1][0], b[2*p+1][1],
                        sW + boff[p] + ko);
            #pragma unroll
            for (int i = 0; i < 4; i++)
                #pragma unroll
                for (int j = 0; j < 8; j++)
                    mma_f16(acc[i][j], a[i], b[j]);
        }
    }

    // ---- epilogue ----
    float*  Cf = (float*)Cv;
    __half* Ch = (__half*)Cv;
    #pragma unroll
    for (int i = 0; i < 4; i++) {
        int row0 = mBase + warp_m * 64 + i * 16 + g;
        #pragma unroll
        for (int j = 0; j < 8; j++) {
            int col = nBase + warp_n * 64 + j * 8 + q * 2;
            float bx = bias[col], by = bias[col + 1];

            #pragma unroll
            for (int half = 0; half < 2; half++) {
                int row = row0 + half * 8;
                float vx = acc[i][j][half * 2 + 0] + bx;
                float vy = acc[i][j][half * 2 + 1] + by;
                if (EPI == 1) {
                    float2 r2 = *(const float2*)(res + (size_t)row * Nn + col);
                    vx += r2.x; vy += r2.y;
                    float2 o; o.x = vx; o.y = vy;
                    *(float2*)(Cf + (size_t)row * Nn + col) = o;
                } else if (EPI == 2) {
                    vx = 0.5f * vx * (1.0f + erff(vx * 0.70710678118654752f));
                    vy = 0.5f * vy * (1.0f + erff(vy * 0.70710678118654752f));
                    *(__half2*)(Ch + (size_t)row * Nn + col) =
                        __floats2half2_rn(vx, vy);
                } else {
                    *(__half2*)(Ch + (size_t)row * Nn + col) =
                        __floats2half2_rn(vx, vy);
                }
            }
        }
    }
}

// ---------------------------------------------------------------------------
// LayerNorm: one block per row of 768, fp16 output
// ---------------------------------------------------------------------------
__global__ __launch_bounds__(256) void ln_kernel(
    const float* __restrict__ x, const float* __restrict__ g,
    const float* __restrict__ b, __half* __restrict__ out)
{
    int row = blockIdx.x;
    const float* xr = x + (size_t)row * EMBED_;
    __half* orow = out + (size_t)row * EMBED_;
    int tid = threadIdx.x;

    float v0 = xr[tid], v1 = xr[tid + 256], v2 = xr[tid + 512];
    float s  = v0 + v1 + v2;
    float s2 = v0 * v0 + v1 * v1 + v2 * v2;

    #pragma unroll
    for (int o = 16; o > 0; o >>= 1) {
        s  += __shfl_xor_sync(0xffffffffu, s,  o);
        s2 += __shfl_xor_sync(0xffffffffu, s2, o);
    }
    __shared__ float sm1[8], sm2[8];
    int warp = tid >> 5, lane = tid & 31;
    if (lane == 0) { sm1[warp] = s; sm2[warp] = s2; }
    __syncthreads();
    float ts = 0.f, ts2 = 0.f;
    #pragma unroll
    for (int w = 0; w < 8; w++) { ts += sm1[w]; ts2 += sm2[w]; }

    float mu  = ts * (1.0f / EMBED_);
    float var = ts2 * (1.0f / EMBED_) - mu * mu;
    float inv = rsqrtf(var + 1e-5f);

    orow[tid      ] = __float2half_rn((v0 - mu) * inv * g[tid      ] + b[tid      ]);
    orow[tid + 256] = __float2half_rn((v1 - mu) * inv * g[tid + 256] + b[tid + 256]);
    orow[tid + 512] = __float2half_rn((v2 - mu) * inv * g[tid + 512] + b[tid + 512]);
}

// ---------------------------------------------------------------------------
// Flash attention, full fp16 (fp32 softmax + accum), P register-resident.
// grid = (N/64 q-tiles, B*HEADS), 128 threads / 4 warps; warp owns 16 q-rows.
// smem (halves, stride 72): Q 64x72 @0; K 2x(64x72) @4608; V 2x @13824.
// ---------------------------------------------------------------------------
#define FB      64
#define TITERS  (N_ / FB)                    // 16
#define FRS     72                           // halves per row
#define FRW     (FRS / 2)                    // 36 words
#define QP_OFF  0
#define K_OFF   (64 * FRS)                   // 4608
#define V_OFF   (3 * 64 * FRS)               // 13824
#define KSTG    (64 * FRS)
#define FLASH_SMEM (5 * 64 * FRS * 2)        // 46080 B

__global__ __launch_bounds__(128, 3) void flash_mma_kernel(
    const __half* __restrict__ qkv, __half* __restrict__ ctx)
{
    extern __shared__ __half fsm[];
    const int tid  = threadIdx.x;
    const int wq   = tid >> 5, lane = tid & 31;
    const int g    = lane >> 2, q = lane & 3;
    const int m3   = lane >> 3, r8 = lane & 7;
    const int qt   = blockIdx.x;
    const int bh   = blockIdx.y;
    const int bb   = bh / HEADS_, h = bh % HEADS_;

    const __half* base = qkv + (size_t)bb * N_ * QKVW_ + h * HD_;
    const uint32_t smb = smem_u32(fsm);

    uint32_t koff[4], voff[4];
    #pragma unroll
    for (int p = 0; p < 4; p++) {
        koff[p] = (uint32_t)((((2 * p + (m3 >> 1)) * 8 + r8) * FRS + (m3 & 1) * 8) * 2);
        voff[p] = (uint32_t)((((m3 & 1) * 8 + r8) * FRS + (2 * p + (m3 >> 1)) * 8) * 2);
    }

    // ---- prologue: group0 = Q + K0 + V0; group1 = K1 + V1 ----
    #pragma unroll
    for (int i = 0; i < 4; i++) {
        int c   = tid + 128 * i;           // 0..511
        int r   = c >> 3;                  // row 0..63
        int c16 = (c & 7) << 3;            // halves 0..56
        const __half* srow = base + (size_t)r * QKVW_;
        CP_ASYNC16(smb + (uint32_t)(K_OFF + r * FRS + c16) * 2u, srow + EMBED_ + c16);
        CP_ASYNC16(smb + (uint32_t)(V_OFF + r * FRS + c16) * 2u, srow + 2 * EMBED_ + c16);
        CP_ASYNC16(smb + (uint32_t)(QP_OFF + r * FRS + c16) * 2u,
                   base + (size_t)(qt * FB + r) * QKVW_ + c16);
    }
    CP_COMMIT();
    #pragma unroll
    for (int i = 0; i < 4; i++) {
        int c   = tid + 128 * i;
        int r   = c >> 3;
        int c16 = (c & 7) << 3;
        const __half* srow = base + (size_t)(FB + r) * QKVW_;
        CP_ASYNC16(smb + (uint32_t)(K_OFF + KSTG + r * FRS + c16) * 2u, srow + EMBED_ + c16);
        CP_ASYNC16(smb + (uint32_t)(V_OFF + KSTG + r * FRS + c16) * 2u, srow + 2 * EMBED_ + c16);
    }
    CP_COMMIT();

    CP_WAIT1();
    __syncthreads();

    // ---- Q fragments (4 ksteps x 4 regs), scaled by 0.125 (exact) ----
    const int r0 = wq * 16 + g;
    const __half2 hs = __float2half2_rn(0.125f);
    uint32_t aQ[4][4];
    {
        const uint32_t* Qw = (const uint32_t*)(fsm + QP_OFF);
        #pragma unroll
        for (int ks = 0; ks < 4; ks++) {
            aQ[ks][0] = Qw[r0 * FRW + ks * 8 + q];
            aQ[ks][1] = Qw[(r0 + 8) * FRW + ks * 8 + q];
            aQ[ks][2] = Qw[r0 * FRW + ks * 8 + 4 + q];
            aQ[ks][3] = Qw[(r0 + 8) * FRW + ks * 8 + 4 + q];
            #pragma unroll
            for (int r = 0; r < 4; r++) {
                __half2 v = *(__half2*)&aQ[ks][r];
                v = __hmul2(v, hs);
                aQ[ks][r] = *(uint32_t*)&v;
            }
        }
    }

    float accO[8][4];
    #pragma unroll
    for (int j = 0; j < 8; j++)
        #pragma unroll
        for (int r = 0; r < 4; r++) accO[j][r] = 0.f;
    float m0 = -1e30f, m1 = -1e30f, l0 = 0.f, l1 = 0.f;

    // ---- kv-tile loop ----
    #pragma unroll 1
    for (int t = 0; t < TITERS; t++) {
        if (t > 0) {
            CP_WAIT1();
            __syncthreads();
        }
        uint32_t kb = smb + (uint32_t)(K_OFF + (t & 1) * KSTG) * 2u;
        uint32_t vb = smb + (uint32_t)(V_OFF + (t & 1) * KSTG) * 2u;

        // S = Q K^T
        float s[8][4];
        #pragma unroll
        for (int j = 0; j < 8; j++)
            #pragma unroll
            for (int r = 0; r < 4; r++) s[j][r] = 0.f;

        #pragma unroll
        for (int ks = 0; ks < 4; ks++) {
            uint32_t b[8][2];
            #pragma unroll
            for (int p = 0; p < 4; p++)
                LDSM_X4(b[2*p][0], b[2*p][1], b[2*p+1][0], b[2*p+1][1],
                        kb + koff[p] + ks * 32);
            #pragma unroll
            for (int j = 0; j < 8; j++)
                mma_f16(s[j], aQ[ks], b[j]);
        }

        // ---- online softmax (rows r0 via s[.][0..1], r0+8 via s[.][2..3]) ----
        float mx0 = -1e30f, mx1 = -1e30f;
        #pragma unroll
        for (int j = 0; j < 8; j++) {
            mx0 = fmaxf(mx0, fmaxf(s[j][0], s[j][1]));
            mx1 = fmaxf(mx1, fmaxf(s[j][2], s[j][3]));
        }
        mx0 = fmaxf(mx0, __shfl_xor_sync(0xffffffffu, mx0, 1));
        mx0 = fmaxf(mx0, __shfl_xor_sync(0xffffffffu, mx0, 2));
        mx1 = fmaxf(mx1, __shfl_xor_sync(0xffffffffu, mx1, 1));
        mx1 = fmaxf(mx1, __shfl_xor_sync(0xffffffffu, mx1, 2));

        float mn0 = fmaxf(m0, mx0), mn1 = fmaxf(m1, mx1);
        float al0 = __expf(m0 - mn0), al1 = __expf(m1 - mn1);
        m0 = mn0; m1 = mn1;

        float rs0 = 0.f, rs1 = 0.f;
        #pragma unroll
        for (int j = 0; j < 8; j++) {
            s[j][0] = __expf(s[j][0] - mn0);
            s[j][1] = __expf(s[j][1] - mn0);
            s[j][2] = __expf(s[j][2] - mn1);
            s[j][3] = __expf(s[j][3] - mn1);
            rs0 += s[j][0] + s[j][1];
            rs1 += s[j][2] + s[j][3];
        }
        rs0 += __shfl_xor_sync(0xffffffffu, rs0, 1);
        rs0 += __shfl_xor_sync(0xffffffffu, rs0, 2);
        rs1 += __shfl_xor_sync(0xffffffffu, rs1, 1);
        rs1 += __shfl_xor_sync(0xffffffffu, rs1, 2);

        l0 = l0 * al0 + rs0;
        l1 = l1 * al1 + rs1;
        #pragma unroll
        for (int j = 0; j < 8; j++) {
            accO[j][0] *= al0; accO[j][1] *= al0;
            accO[j][2] *= al1; accO[j][3] *= al1;
        }

        // ---- P stays in registers: C-frag of S == A-frag of P ----
        // A-frag for kstep ks: a0=(row g, k lo), a1=(row g+8, k lo),
        //                      a2=(row g, k hi), a3=(row g+8, k hi)
        #pragma unroll
        for (int ks = 0; ks < 4; ks++) {
            uint32_t aP[4];
            __half2 p0 = __floats2half2_rn(s[2*ks][0],   s[2*ks][1]);
            __half2 p1 = __floats2half2_rn(s[2*ks][2],   s[2*ks][3]);
            __half2 p2 = __floats2half2_rn(s[2*ks+1][0], s[2*ks+1][1]);
            __half2 p3 = __floats2half2_rn(s[2*ks+1][2], s[2*ks+1][3]);
            aP[0] = *(uint32_t*)&p0;
            aP[1] = *(uint32_t*)&p1;
            aP[2] = *(uint32_t*)&p2;
            aP[3] = *(uint32_t*)&p3;
            uint32_t b[8][2];
            #pragma unroll
            for (int p = 0; p < 4; p++)
                LDSM_X4T(b[2*p][0], b[2*p][1], b[2*p+1][0], b[2*p+1][1],
                         vb + voff[p] + (uint32_t)(ks * 16 * FRS * 2));
            #pragma unroll
            for (int j = 0; j < 8; j++)
                mma_f16(accO[j], aP, b[j]);
        }

        __syncthreads();   // KV slot reads done

        // prefetch tile t+2 into slot (t&1)
        if (t + 2 < TITERS) {
            const __half* src = base + (size_t)((t + 2) * FB) * QKVW_;
            uint32_t kd = smb + (uint32_t)(K_OFF + (t & 1) * KSTG) * 2u;
            uint32_t vd = smb + (uint32_t)(V_OFF + (t & 1) * KSTG) * 2u;
            #pragma unroll
            for (int i = 0; i < 4; i++) {
                int c   = tid + 128 * i;
                int r   = c >> 3;
                int c16 = (c & 7) << 3;
                const __half* srow = src + (size_t)r * QKVW_;
                CP_ASYNC16(kd + (uint32_t)(r * FRS + c16) * 2u, srow + EMBED_ + c16);
                CP_ASYNC16(vd + (uint32_t)(r * FRS + c16) * 2u, srow + 2 * EMBED_ + c16);
            }
        }
        CP_COMMIT();
    }

    // ---- output (fp16 ctx) ----
    float inv0 = 1.0f / l0, inv1 = 1.0f / l1;
    size_t tok0 = (size_t)(bb * N_ + qt * FB + r0);
    #pragma unroll
    for (int j = 0; j < 8; j++) {
        int col = h * HD_ + j * 8 + 2 * q;
        *(__half2*)(ctx + tok0 * EMBED_ + col) =
            __floats2half2_rn(accO[j][0] * inv0, accO[j][1] * inv0);
        *(__half2*)(ctx + (tok0 + 8) * EMBED_ + col) =
            __floats2half2_rn(accO[j][2] * inv1, accO[j][3] * inv1);
    }
}

// ---------------------------------------------------------------------------
// launch
// ---------------------------------------------------------------------------
extern "C" void kernel_launch(void* const* d_in, const int* in_sizes, int n_in,
                              void* d_out, int out_size)
{
    const float* x      = (const float*)d_in[0];
    const float* ln1_g  = (const float*)d_in[1];
    const float* ln1_b  = (const float*)d_in[2];
    const float* qkv_w  = (const float*)d_in[3];
    const float* qkv_b  = (const float*)d_in[4];
    const float* proj_w = (const float*)d_in[5];
    const float* proj_b = (const float*)d_in[6];
    const float* ln2_g  = (const float*)d_in[7];
    const float* ln2_b  = (const float*)d_in[8];
    const float* fc1_w  = (const float*)d_in[9];
    const float* fc1_b  = (const float*)d_in[10];
    const float* fc2_w  = (const float*)d_in[11];
    const float* fc2_b  = (const float*)d_in[12];
    float* out = (float*)d_out;

    __half *h16, *qkv16, *ctx16, *h216, *ffn16, *wq16, *wp16, *w116, *w216;
    float *x1;
    cudaGetSymbolAddress((void**)&h16,   g_h16);
    cudaGetSymbolAddress((void**)&qkv16, g_qkv16);
    cudaGetSymbolAddress((void**)&ctx16, g_ctx16);
    cudaGetSymbolAddress((void**)&x1,    g_x1);
    cudaGetSymbolAddress((void**)&h216,  g_h216);
    cudaGetSymbolAddress((void**)&ffn16, g_ffn16);
    cudaGetSymbolAddress((void**)&wq16,  g_wq16);
    cudaGetSymbolAddress((void**)&wp16,  g_wp16);
    cudaGetSymbolAddress((void**)&w116,  g_w116);
    cudaGetSymbolAddress((void**)&w216,  g_w216);

    cudaFuncSetAttribute(flash_mma_kernel,
                         cudaFuncAttributeMaxDynamicSharedMemorySize, FLASH_SMEM);
    cudaFuncSetAttribute(mma_gemm<0>,
                         cudaFuncAttributeMaxDynamicSharedMemorySize, GEMM_DSMEM);
    cudaFuncSetAttribute(mma_gemm<1>,
                         cudaFuncAttributeMaxDynamicSharedMemorySize, GEMM_DSMEM);
    cudaFuncSetAttribute(mma_gemm<2>,
                         cudaFuncAttributeMaxDynamicSharedMemorySize, GEMM_DSMEM);

    // all weights -> fp16, one launch
    f2h_all_kernel<<<(NWTOT + 255) / 256, 256>>>(
        qkv_w, proj_w, fc1_w, fc2_w, wq16, wp16, w116, w216);

    // ln1 (fp16 out)
    ln_kernel<<<TOKENS_, 256>>>(x, ln1_g, ln1_b, h16);
    // qkv = h @ qkv_w^T + b  (fp16 out)
    mma_gemm<0><<<dim3(QKVW_ / 128, TOKENS_ / 128), 128, GEMM_DSMEM>>>(
        h16, wq16, qkv_b, nullptr, qkv16, TOKENS_, QKVW_, EMBED_);
    // attention (fp16 ctx out)
    flash_mma_kernel<<<dim3(N_ / FB, B_ * HEADS_), 128, FLASH_SMEM>>>(qkv16, ctx16);
    // x1 = x + ctx @ proj_w^T + b  (fp32 out)
    mma_gemm<1><<<dim3(EMBED_ / 128, TOKENS_ / 128), 128, GEMM_DSMEM>>>(
        ctx16, wp16, proj_b, x, x1, TOKENS_, EMBED_, EMBED_);
    // ln2 (fp16 out)
    ln_kernel<<<TOKENS_, 256>>>(x1, ln2_g, ln2_b, h216);
    // ffn = gelu(h2 @ fc1_w^T + b)  (fp16 out)
    mma_gemm<2><<<dim3(HIDDEN_ / 128, TOKENS_ / 128), 128, GEMM_DSMEM>>>(
        h216, w116, fc1_b, nullptr, ffn16, TOKENS_, HIDDEN_, EMBED_);
    // out = x1 + ffn @ fc2_w^T + b  (fp32 out)
    mma_gemm<1><<<dim3(EMBED_ / 128, TOKENS_ / 128), 128, GEMM_DSMEM>>>(
        ffn16, w216, fc2_b, x1, out, TOKENS_, EMBED_, HIDDEN_);
}

// round 14
// speedup vs baseline: 1.0601x; 1.0601x over previous
#include <cuda_runtime.h>
#include <cuda_fp16.h>
#include <math.h>
#include <stdint.h>

// ---------------------------------------------------------------------------
// TransformerBlock: B=8, N=1024, EMBED=768, HEADS=12, HEAD_DIM=64, HIDDEN=3072
// GEMMs: mma.sync.m16n8k16 fp16 + ldmatrix, 4 warps x (64x64), BK=32,
// 4-stage cp.async (R9 measured-best). Flash: full fp16, P register-resident,
// 4 CTAs/SM attempt (128-reg cap).
// ---------------------------------------------------------------------------

#define B_      8
#define N_      1024
#define EMBED_  768
#define HEADS_  12
#define HD_     64
#define HIDDEN_ 3072
#define TOKENS_ (B_ * N_)          // 8192
#define QKVW_   (3 * EMBED_)       // 2304

// ---- scratch (static device globals: allocation-free) ----
__device__ __half g_h16  [TOKENS_ * EMBED_];
__device__ __half g_qkv16[TOKENS_ * QKVW_];
__device__ __half g_ctx16[TOKENS_ * EMBED_];
__device__ float  g_x1   [TOKENS_ * EMBED_];
__device__ __half g_h216 [TOKENS_ * EMBED_];
__device__ __half g_ffn16[TOKENS_ * HIDDEN_];
// fp16 weights
__device__ __half g_wq16 [QKVW_  * EMBED_];
__device__ __half g_wp16 [EMBED_ * EMBED_];
__device__ __half g_w116 [HIDDEN_ * EMBED_];
__device__ __half g_w216 [EMBED_ * HIDDEN_];

// ---------------------------------------------------------------------------
// helpers
// ---------------------------------------------------------------------------
__device__ __forceinline__ uint32_t smem_u32(const void* p) {
    uint32_t a;
    asm("{ .reg .u64 t; cvta.to.shared.u64 t, %1; cvt.u32.u64 %0, t; }"
        : "=r"(a) : "l"(p));
    return a;
}
#define CP_ASYNC16(dst, src) \
    asm volatile("cp.async.cg.shared.global [%0], [%1], 16;" \
                 :: "r"(dst), "l"(src) : "memory")
#define CP_COMMIT()  asm volatile("cp.async.commit_group;" ::: "memory")
#define CP_WAIT2()   asm volatile("cp.async.wait_group 2;" ::: "memory")
#define CP_WAIT1()   asm volatile("cp.async.wait_group 1;" ::: "memory")

#define LDSM_X4(r0, r1, r2, r3, addr) \
    asm volatile("ldmatrix.sync.aligned.m8n8.x4.shared.b16 {%0,%1,%2,%3}, [%4];" \
                 : "=r"(r0), "=r"(r1), "=r"(r2), "=r"(r3) : "r"(addr))
#define LDSM_X4T(r0, r1, r2, r3, addr) \
    asm volatile("ldmatrix.sync.aligned.m8n8.x4.trans.shared.b16 {%0,%1,%2,%3}, [%4];" \
                 : "=r"(r0), "=r"(r1), "=r"(r2), "=r"(r3) : "r"(addr))

__device__ __forceinline__ void mma_f16(float* d, const uint32_t* a,
                                        const uint32_t* b) {
    asm volatile(
        "mma.sync.aligned.m16n8k16.row.col.f32.f16.f16.f32 "
        "{%0,%1,%2,%3}, {%4,%5,%6,%7}, {%8,%9}, {%0,%1,%2,%3};"
        : "+f"(d[0]), "+f"(d[1]), "+f"(d[2]), "+f"(d[3])
        : "r"(a[0]), "r"(a[1]), "r"(a[2]), "r"(a[3]), "r"(b[0]), "r"(b[1]));
}

// ---------------------------------------------------------------------------
// merged fp32 -> fp16 weight convert (all 4 weights, one launch)
// ---------------------------------------------------------------------------
#define NW1 (QKVW_  * EMBED_  / 4)
#define NW2 (EMBED_ * EMBED_  / 4)
#define NW3 (HIDDEN_ * EMBED_ / 4)
#define NW4 (EMBED_ * HIDDEN_ / 4)
#define NWTOT (NW1 + NW2 + NW3 + NW4)

__global__ __launch_bounds__(256) void f2h_all_kernel(
    const float* __restrict__ w1, const float* __restrict__ w2,
    const float* __restrict__ w3, const float* __restrict__ w4,
    __half* __restrict__ o1, __half* __restrict__ o2,
    __half* __restrict__ o3, __half* __restrict__ o4)
{
    int i = blockIdx.x * blockDim.x + threadIdx.x;
    if (i >= NWTOT) return;
    const float* src; __half* dst; int j = i;
    if (j < NW1)                { src = w1; dst = o1; }
    else if ((j -= NW1) < NW2)  { src = w2; dst = o2; }
    else if ((j -= NW2) < NW3)  { src = w3; dst = o3; }
    else                        { j -= NW3; src = w4; dst = o4; }
    float4 v = ((const float4*)src)[j];
    __half2 h0 = __floats2half2_rn(v.x, v.y);
    __half2 h1 = __floats2half2_rn(v.z, v.w);
    uint2 o;
    o.x = *(uint32_t*)&h0;
    o.y = *(uint32_t*)&h1;
    ((uint2*)dst)[j] = o;
}

// ---------------------------------------------------------------------------
// fp16 mma GEMM with ldmatrix: C = A @ W^T + bias (+res / +gelu)
// EPI: 0 = bias (fp16 out), 1 = bias + residual (fp32 out),
//      2 = bias + exact GELU (fp16 out)
// CTA 128x128, BK=32 halves, 128 thr / 4 warps (64x64/warp), 4 stages.
// ---------------------------------------------------------------------------
#define BK          32
#define RSH         40                          // row stride in halves
#define MAT_HALVES  (128 * RSH)                 // 5120
#define STAGE_HALVES (2 * MAT_HALVES)           // 10240
#define STAGES      4
#define GEMM_DSMEM  (STAGES * STAGE_HALVES * 2) // 81920 B

template <int EPI>
__global__ __launch_bounds__(128, 2) void mma_gemm(
    const __half* __restrict__ A, const __half* __restrict__ W,
    const float* __restrict__ bias, const float* __restrict__ res,
    void* __restrict__ Cv, int M, int Nn, int K)
{
    extern __shared__ __half smh[];

    const int tid  = threadIdx.x;
    const int wid  = tid >> 5, lane = tid & 31;
    const int mBase = blockIdx.y * 128;
    const int nBase = blockIdx.x * 128;
    const int warp_m = wid & 1;
    const int warp_n = wid >> 1;
    const int g = lane >> 2;
    const int q = lane & 3;
    const int m3 = lane >> 3, r8 = lane & 7;

    const uint32_t sm_base = smem_u32(smh);

    // cp.async mapping: 4 chunks (16B) per thread per matrix per ktile
    int rL[4], cL[4];
    #pragma unroll
    for (int it = 0; it < 4; it++) {
        int flat = tid + it * 128;
        rL[it] = flat >> 2;
        cL[it] = (flat & 3) << 3;    // halves
    }
    const __half* Arow = A + (size_t)mBase * K;
    const __half* Wrow = W + (size_t)nBase * K;

    const int nK = K / BK;

    // ldmatrix byte offsets (within a stage's A / W matrix)
    uint32_t aoff[4], boff[4];
    #pragma unroll
    for (int i = 0; i < 4; i++)
        aoff[i] = (uint32_t)(((warp_m * 64 + i * 16 + (m3 & 1) * 8 + r8) * RSH
                              + (m3 >> 1) * 8) * 2);
    #pragma unroll
    for (int p = 0; p < 4; p++)
        boff[p] = (uint32_t)(((warp_n * 64 + (2 * p + (m3 >> 1)) * 8 + r8) * RSH
                              + (m3 & 1) * 8) * 2);

    float acc[4][8][4];
    #pragma unroll
    for (int i = 0; i < 4; i++)
        #pragma unroll
        for (int j = 0; j < 8; j++)
            #pragma unroll
            for (int r = 0; r < 4; r++) acc[i][j][r] = 0.f;

    // ---- prologue: 3 stages ----
    #pragma unroll
    for (int t = 0; t < 3; t++) {
        uint32_t sb = sm_base + (uint32_t)(t * STAGE_HALVES) * 2u;
        int k0 = t * BK;
        #pragma unroll
        for (int it = 0; it < 4; it++) {
            uint32_t doff = (uint32_t)(rL[it] * RSH + cL[it]) * 2u;
            CP_ASYNC16(sb + doff,                   Arow + (size_t)rL[it] * K + k0 + cL[it]);
            CP_ASYNC16(sb + MAT_HALVES * 2u + doff, Wrow + (size_t)rL[it] * K + k0 + cL[it]);
        }
        CP_COMMIT();
    }

    // ---- mainloop ----
    #pragma unroll 1
    for (int kt = 0; kt < nK; kt++) {
        CP_WAIT2();
        __syncthreads();

        int ft = kt + 3;
        if (ft < nK) {
            uint32_t sb = sm_base + (uint32_t)((ft & 3) * STAGE_HALVES) * 2u;
            int k0 = ft * BK;
            #pragma unroll
            for (int it = 0; it < 4; it++) {
                uint32_t doff = (uint32_t)(rL[it] * RSH + cL[it]) * 2u;
                CP_ASYNC16(sb + doff,                   Arow + (size_t)rL[it] * K + k0 + cL[it]);
                CP_ASYNC16(sb + MAT_HALVES * 2u + doff, Wrow + (size_t)rL[it] * K + k0 + cL[it]);
            }
        }
        CP_COMMIT();

        uint32_t sA = sm_base + (uint32_t)((kt & 3) * STAGE_HALVES) * 2u;
        uint32_t sW = sA + MAT_HALVES * 2u;

        #pragma unroll
        for (int ks = 0; ks < 2; ks++) {
            uint32_t ko = (uint32_t)(ks * 32);   // 16 halves
            uint32_t a[4][4], b[8][2];
            #pragma unroll
            for (int i = 0; i < 4; i++)
                LDSM_X4(a[i][0], a[i][1], a[i][2], a[i][3], sA + aoff[i] + ko);
            #pragma unroll
            for (int p = 0; p < 4; p++)
                LDSM_X4(b[2*p][0], b[2*p][1], b[2*p+1][0], b[2*p+1][1],
                        sW + boff[p] + ko);
            #pragma unroll
            for (int i = 0; i < 4; i++)
                #pragma unroll
                for (int j = 0; j < 8; j++)
                    mma_f16(acc[i][j], a[i], b[j]);
        }
    }

    // ---- epilogue ----
    float*  Cf = (float*)Cv;
    __half* Ch = (__half*)Cv;
    #pragma unroll
    for (int i = 0; i < 4; i++) {
        int row0 = mBase + warp_m * 64 + i * 16 + g;
        #pragma unroll
        for (int j = 0; j < 8; j++) {
            int col = nBase + warp_n * 64 + j * 8 + q * 2;
            float bx = bias[col], by = bias[col + 1];

            #pragma unroll
            for (int half = 0; half < 2; half++) {
                int row = row0 + half * 8;
                float vx = acc[i][j][half * 2 + 0] + bx;
                float vy = acc[i][j][half * 2 + 1] + by;
                if (EPI == 1) {
                    float2 r2 = *(const float2*)(res + (size_t)row * Nn + col);
                    vx += r2.x; vy += r2.y;
                    float2 o; o.x = vx; o.y = vy;
                    *(float2*)(Cf + (size_t)row * Nn + col) = o;
                } else if (EPI == 2) {
                    vx = 0.5f * vx * (1.0f + erff(vx * 0.70710678118654752f));
                    vy = 0.5f * vy * (1.0f + erff(vy * 0.70710678118654752f));
                    *(__half2*)(Ch + (size_t)row * Nn + col) =
                        __floats2half2_rn(vx, vy);
                } else {
                    *(__half2*)(Ch + (size_t)row * Nn + col) =
                        __floats2half2_rn(vx, vy);
                }
            }
        }
    }
}

// ---------------------------------------------------------------------------
// LayerNorm: one block per row of 768, fp16 output
// ---------------------------------------------------------------------------
__global__ __launch_bounds__(256) void ln_kernel(
    const float* __restrict__ x, const float* __restrict__ g,
    const float* __restrict__ b, __half* __restrict__ out)
{
    int row = blockIdx.x;
    const float* xr = x + (size_t)row * EMBED_;
    __half* orow = out + (size_t)row * EMBED_;
    int tid = threadIdx.x;

    float v0 = xr[tid], v1 = xr[tid + 256], v2 = xr[tid + 512];
    float s  = v0 + v1 + v2;
    float s2 = v0 * v0 + v1 * v1 + v2 * v2;

    #pragma unroll
    for (int o = 16; o > 0; o >>= 1) {
        s  += __shfl_xor_sync(0xffffffffu, s,  o);
        s2 += __shfl_xor_sync(0xffffffffu, s2, o);
    }
    __shared__ float sm1[8], sm2[8];
    int warp = tid >> 5, lane = tid & 31;
    if (lane == 0) { sm1[warp] = s; sm2[warp] = s2; }
    __syncthreads();
    float ts = 0.f, ts2 = 0.f;
    #pragma unroll
    for (int w = 0; w < 8; w++) { ts += sm1[w]; ts2 += sm2[w]; }

    float mu  = ts * (1.0f / EMBED_);
    float var = ts2 * (1.0f / EMBED_) - mu * mu;
    float inv = rsqrtf(var + 1e-5f);

    orow[tid      ] = __float2half_rn((v0 - mu) * inv * g[tid      ] + b[tid      ]);
    orow[tid + 256] = __float2half_rn((v1 - mu) * inv * g[tid + 256] + b[tid + 256]);
    orow[tid + 512] = __float2half_rn((v2 - mu) * inv * g[tid + 512] + b[tid + 512]);
}

// ---------------------------------------------------------------------------
// Flash attention, full fp16 (fp32 softmax + accum), P register-resident.
// grid = (N/64 q-tiles, B*HEADS), 128 threads / 4 warps; warp owns 16 q-rows.
// smem (halves, stride 72): Q 64x72 @0; K 2x(64x72) @4608; V 2x @13824.
// 4 CTAs/SM attempt via 128-reg cap.
// ---------------------------------------------------------------------------
#define FB      64
#define TITERS  (N_ / FB)                    // 16
#define FRS     72                           // halves per row
#define FRW     (FRS / 2)                    // 36 words
#define QP_OFF  0
#define K_OFF   (64 * FRS)                   // 4608
#define V_OFF   (3 * 64 * FRS)               // 13824
#define KSTG    (64 * FRS)
#define FLASH_SMEM (5 * 64 * FRS * 2)        // 46080 B

__global__ __launch_bounds__(128, 4) void flash_mma_kernel(
    const __half* __restrict__ qkv, __half* __restrict__ ctx)
{
    extern __shared__ __half fsm[];
    const int tid  = threadIdx.x;
    const int wq   = tid >> 5, lane = tid & 31;
    const int g    = lane >> 2, q = lane & 3;
    const int m3   = lane >> 3, r8 = lane & 7;
    const int qt   = blockIdx.x;
    const int bh   = blockIdx.y;
    const int bb   = bh / HEADS_, h = bh % HEADS_;

    const __half* base = qkv + (size_t)bb * N_ * QKVW_ + h * HD_;
    const uint32_t smb = smem_u32(fsm);

    uint32_t koff[4], voff[4];
    #pragma unroll
    for (int p = 0; p < 4; p++) {
        koff[p] = (uint32_t)((((2 * p + (m3 >> 1)) * 8 + r8) * FRS + (m3 & 1) * 8) * 2);
        voff[p] = (uint32_t)((((m3 & 1) * 8 + r8) * FRS + (2 * p + (m3 >> 1)) * 8) * 2);
    }

    // ---- prologue: group0 = Q + K0 + V0; group1 = K1 + V1 ----
    #pragma unroll
    for (int i = 0; i < 4; i++) {
        int c   = tid + 128 * i;           // 0..511
        int r   = c >> 3;                  // row 0..63
        int c16 = (c & 7) << 3;            // halves 0..56
        const __half* srow = base + (size_t)r * QKVW_;
        CP_ASYNC16(smb + (uint32_t)(K_OFF + r * FRS + c16) * 2u, srow + EMBED_ + c16);
        CP_ASYNC16(smb + (uint32_t)(V_OFF + r * FRS + c16) * 2u, srow + 2 * EMBED_ + c16);
        CP_ASYNC16(smb + (uint32_t)(QP_OFF + r * FRS + c16) * 2u,
                   base + (size_t)(qt * FB + r) * QKVW_ + c16);
    }
    CP_COMMIT();
    #pragma unroll
    for (int i = 0; i < 4; i++) {
        int c   = tid + 128 * i;
        int r   = c >> 3;
        int c16 = (c & 7) << 3;
        const __half* srow = base + (size_t)(FB + r) * QKVW_;
        CP_ASYNC16(smb + (uint32_t)(K_OFF + KSTG + r * FRS + c16) * 2u, srow + EMBED_ + c16);
        CP_ASYNC16(smb + (uint32_t)(V_OFF + KSTG + r * FRS + c16) * 2u, srow + 2 * EMBED_ + c16);
    }
    CP_COMMIT();

    CP_WAIT1();
    __syncthreads();

    // ---- Q fragments (4 ksteps x 4 regs), scaled by 0.125 (exact) ----
    const int r0 = wq * 16 + g;
    const __half2 hs = __float2half2_rn(0.125f);
    uint32_t aQ[4][4];
    {
        const uint32_t* Qw = (const uint32_t*)(fsm + QP_OFF);
        #pragma unroll
        for (int ks = 0; ks < 4; ks++) {
            aQ[ks][0] = Qw[r0 * FRW + ks * 8 + q];
            aQ[ks][1] = Qw[(r0 + 8) * FRW + ks * 8 + q];
            aQ[ks][2] = Qw[r0 * FRW + ks * 8 + 4 + q];
            aQ[ks][3] = Qw[(r0 + 8) * FRW + ks * 8 + 4 + q];
            #pragma unroll
            for (int r = 0; r < 4; r++) {
                __half2 v = *(__half2*)&aQ[ks][r];
                v = __hmul2(v, hs);
                aQ[ks][r] = *(uint32_t*)&v;
            }
        }
    }

    float accO[8][4];
    #pragma unroll
    for (int j = 0; j < 8; j++)
        #pragma unroll
        for (int r = 0; r < 4; r++) accO[j][r] = 0.f;
    float m0 = -1e30f, m1 = -1e30f, l0 = 0.f, l1 = 0.f;

    // ---- kv-tile loop ----
    #pragma unroll 1
    for (int t = 0; t < TITERS; t++) {
        if (t > 0) {
            CP_WAIT1();
            __syncthreads();
        }
        uint32_t kb = smb + (uint32_t)(K_OFF + (t & 1) * KSTG) * 2u;
        uint32_t vb = smb + (uint32_t)(V_OFF + (t & 1) * KSTG) * 2u;

        // S = Q K^T
        float s[8][4];
        #pragma unroll
        for (int j = 0; j < 8; j++)
            #pragma unroll
            for (int r = 0; r < 4; r++) s[j][r] = 0.f;

        #pragma unroll
        for (int ks = 0; ks < 4; ks++) {
            uint32_t b[8][2];
            #pragma unroll
            for (int p = 0; p < 4; p++)
                LDSM_X4(b[2*p][0], b[2*p][1], b[2*p+1][0], b[2*p+1][1],
                        kb + koff[p] + ks * 32);
            #pragma unroll
            for (int j = 0; j < 8; j++)
                mma_f16(s[j], aQ[ks], b[j]);
        }

        // ---- online softmax (rows r0 via s[.][0..1], r0+8 via s[.][2..3]) ----
        float mx0 = -1e30f, mx1 = -1e30f;
        #pragma unroll
        for (int j = 0; j < 8; j++) {
            mx0 = fmaxf(mx0, fmaxf(s[j][0], s[j][1]));
            mx1 = fmaxf(mx1, fmaxf(s[j][2], s[j][3]));
        }
        mx0 = fmaxf(mx0, __shfl_xor_sync(0xffffffffu, mx0, 1));
        mx0 = fmaxf(mx0, __shfl_xor_sync(0xffffffffu, mx0, 2));
        mx1 = fmaxf(mx1, __shfl_xor_sync(0xffffffffu, mx1, 1));
        mx1 = fmaxf(mx1, __shfl_xor_sync(0xffffffffu, mx1, 2));

        float mn0 = fmaxf(m0, mx0), mn1 = fmaxf(m1, mx1);
        float al0 = __expf(m0 - mn0), al1 = __expf(m1 - mn1);
        m0 = mn0; m1 = mn1;

        float rs0 = 0.f, rs1 = 0.f;
        #pragma unroll
        for (int j = 0; j < 8; j++) {
            s[j][0] = __expf(s[j][0] - mn0);
            s[j][1] = __expf(s[j][1] - mn0);
            s[j][2] = __expf(s[j][2] - mn1);
            s[j][3] = __expf(s[j][3] - mn1);
            rs0 += s[j][0] + s[j][1];
            rs1 += s[j][2] + s[j][3];
        }
        rs0 += __shfl_xor_sync(0xffffffffu, rs0, 1);
        rs0 += __shfl_xor_sync(0xffffffffu, rs0, 2);
        rs1 += __shfl_xor_sync(0xffffffffu, rs1, 1);
        rs1 += __shfl_xor_sync(0xffffffffu, rs1, 2);

        l0 = l0 * al0 + rs0;
        l1 = l1 * al1 + rs1;
        #pragma unroll
        for (int j = 0; j < 8; j++) {
            accO[j][0] *= al0; accO[j][1] *= al0;
            accO[j][2] *= al1; accO[j][3] *= al1;
        }

        // ---- P stays in registers: C-frag of S == A-frag of P ----
        #pragma unroll
        for (int ks = 0; ks < 4; ks++) {
            uint32_t aP[4];
            __half2 p0 = __floats2half2_rn(s[2*ks][0],   s[2*ks][1]);
            __half2 p1 = __floats2half2_rn(s[2*ks][2],   s[2*ks][3]);
            __half2 p2 = __floats2half2_rn(s[2*ks+1][0], s[2*ks+1][1]);
            __half2 p3 = __floats2half2_rn(s[2*ks+1][2], s[2*ks+1][3]);
            aP[0] = *(uint32_t*)&p0;
            aP[1] = *(uint32_t*)&p1;
            aP[2] = *(uint32_t*)&p2;
            aP[3] = *(uint32_t*)&p3;
            uint32_t b[8][2];
            #pragma unroll
            for (int p = 0; p < 4; p++)
                LDSM_X4T(b[2*p][0], b[2*p][1], b[2*p+1][0], b[2*p+1][1],
                         vb + voff[p] + (uint32_t)(ks * 16 * FRS * 2));
            #pragma unroll
            for (int j = 0; j < 8; j++)
                mma_f16(accO[j], aP, b[j]);
        }

        __syncthreads();   // KV slot reads done

        // prefetch tile t+2 into slot (t&1)
        if (t + 2 < TITERS) {
            const __half* src = base + (size_t)((t + 2) * FB) * QKVW_;
            uint32_t kd = smb + (uint32_t)(K_OFF + (t & 1) * KSTG) * 2u;
            uint32_t vd = smb + (uint32_t)(V_OFF + (t & 1) * KSTG) * 2u;
            #pragma unroll
            for (int i = 0; i < 4; i++) {
                int c   = tid + 128 * i;
                int r   = c >> 3;
                int c16 = (c & 7) << 3;
                const __half* srow = src + (size_t)r * QKVW_;
                CP_ASYNC16(kd + (uint32_t)(r * FRS + c16) * 2u, srow + EMBED_ + c16);
                CP_ASYNC16(vd + (uint32_t)(r * FRS + c16) * 2u, srow + 2 * EMBED_ + c16);
            }
        }
        CP_COMMIT();
    }

    // ---- output (fp16 ctx) ----
    float inv0 = 1.0f / l0, inv1 = 1.0f / l1;
    size_t tok0 = (size_t)(bb * N_ + qt * FB + r0);
    #pragma unroll
    for (int j = 0; j < 8; j++) {
        int col = h * HD_ + j * 8 + 2 * q;
        *(__half2*)(ctx + tok0 * EMBED_ + col) =
            __floats2half2_rn(accO[j][0] * inv0, accO[j][1] * inv0);
        *(__half2*)(ctx + (tok0 + 8) * EMBED_ + col) =
            __floats2half2_rn(accO[j][2] * inv1, accO[j][3] * inv1);
    }
}

// ---------------------------------------------------------------------------
// launch
// ---------------------------------------------------------------------------
extern "C" void kernel_launch(void* const* d_in, const int* in_sizes, int n_in,
                              void* d_out, int out_size)
{
    const float* x      = (const float*)d_in[0];
    const float* ln1_g  = (const float*)d_in[1];
    const float* ln1_b  = (const float*)d_in[2];
    const float* qkv_w  = (const float*)d_in[3];
    const float* qkv_b  = (const float*)d_in[4];
    const float* proj_w = (const float*)d_in[5];
    const float* proj_b = (const float*)d_in[6];
    const float* ln2_g  = (const float*)d_in[7];
    const float* ln2_b  = (const float*)d_in[8];
    const float* fc1_w  = (const float*)d_in[9];
    const float* fc1_b  = (const float*)d_in[10];
    const float* fc2_w  = (const float*)d_in[11];
    const float* fc2_b  = (const float*)d_in[12];
    float* out = (float*)d_out;

    __half *h16, *qkv16, *ctx16, *h216, *ffn16, *wq16, *wp16, *w116, *w216;
    float *x1;
    cudaGetSymbolAddress((void**)&h16,   g_h16);
    cudaGetSymbolAddress((void**)&qkv16, g_qkv16);
    cudaGetSymbolAddress((void**)&ctx16, g_ctx16);
    cudaGetSymbolAddress((void**)&x1,    g_x1);
    cudaGetSymbolAddress((void**)&h216,  g_h216);
    cudaGetSymbolAddress((void**)&ffn16, g_ffn16);
    cudaGetSymbolAddress((void**)&wq16,  g_wq16);
    cudaGetSymbolAddress((void**)&wp16,  g_wp16);
    cudaGetSymbolAddress((void**)&w116,  g_w116);
    cudaGetSymbolAddress((void**)&w216,  g_w216);

    cudaFuncSetAttribute(flash_mma_kernel,
                         cudaFuncAttributeMaxDynamicSharedMemorySize, FLASH_SMEM);
    cudaFuncSetAttribute(mma_gemm<0>,
                         cudaFuncAttributeMaxDynamicSharedMemorySize, GEMM_DSMEM);
    cudaFuncSetAttribute(mma_gemm<1>,
                         cudaFuncAttributeMaxDynamicSharedMemorySize, GEMM_DSMEM);
    cudaFuncSetAttribute(mma_gemm<2>,
                         cudaFuncAttributeMaxDynamicSharedMemorySize, GEMM_DSMEM);

    // all weights -> fp16, one launch
    f2h_all_kernel<<<(NWTOT + 255) / 256, 256>>>(
        qkv_w, proj_w, fc1_w, fc2_w, wq16, wp16, w116, w216);

    // ln1 (fp16 out)
    ln_kernel<<<TOKENS_, 256>>>(x, ln1_g, ln1_b, h16);
    // qkv = h @ qkv_w^T + b  (fp16 out)
    mma_gemm<0><<<dim3(QKVW_ / 128, TOKENS_ / 128), 128, GEMM_DSMEM>>>(
        h16, wq16, qkv_b, nullptr, qkv16, TOKENS_, QKVW_, EMBED_);
    // attention (fp16 ctx out)
    flash_mma_kernel<<<dim3(N_ / FB, B_ * HEADS_), 128, FLASH_SMEM>>>(qkv16, ctx16);
    // x1 = x + ctx @ proj_w^T + b  (fp32 out)
    mma_gemm<1><<<dim3(EMBED_ / 128, TOKENS_ / 128), 128, GEMM_DSMEM>>>(
        ctx16, wp16, proj_b, x, x1, TOKENS_, EMBED_, EMBED_);
    // ln2 (fp16 out)
    ln_kernel<<<TOKENS_, 256>>>(x1, ln2_g, ln2_b, h216);
    // ffn = gelu(h2 @ fc1_w^T + b)  (fp16 out)
    mma_gemm<2><<<dim3(HIDDEN_ / 128, TOKENS_ / 128), 128, GEMM_DSMEM>>>(
        h216, w116, fc1_b, nullptr, ffn16, TOKENS_, HIDDEN_, EMBED_);
    // out = x1 + ffn @ fc2_w^T + b  (fp32 out)
    mma_gemm<1><<<dim3(EMBED_ / 128, TOKENS_ / 128), 128, GEMM_DSMEM>>>(
        ffn16, w216, fc2_b, x1, out, TOKENS_, EMBED_, HIDDEN_);
}